// round 8
// baseline (speedup 1.0000x reference)
#include <cuda_runtime.h>
#include <cstdint>

#define NB    128
#define NPRI  32768
#define TOPK  400
#define KEEPK 200
#define T3    1024
#define WORDS 13
#define CONF_T 0.5f
#define NMS_T  0.5f
#define BIGNEG -1000000000.0f
#define HBINS 512
#define HBASE 12224u          // order_f(0.5) >> 18
#define SEGS  16
#define SEGBOX (NPRI / SEGS)
#define GTOT  2896            // sum_{jb=0..12} min(400,(jb+1)*32) = 2496+400
#define GPW   91              // ceil(GTOT/32)

__device__ unsigned           g_score[NB * NPRI];
__device__ unsigned long long g_cand[NB * NPRI];
__device__ unsigned           g_hist[NB * HBINS];

__device__ __forceinline__ unsigned order_f(float f) {
    unsigned u = __float_as_uint(f);
    return (u & 0x80000000u) ? ~u : (u | 0x80000000u);
}
__device__ __forceinline__ float unorder_f(unsigned u) {
    unsigned v = (u & 0x80000000u) ? (u ^ 0x80000000u) : ~u;
    return __uint_as_float(v);
}

// ============ K1: stream pred, emit ordered scores + 512-bin histogram ======
__global__ __launch_bounds__(256)
void k1_score(const float* __restrict__ pred) {
    const int b   = blockIdx.x >> 4;
    const int seg = blockIdx.x & 15;
    __shared__ unsigned sh[HBINS];
    sh[threadIdx.x] = 0; sh[threadIdx.x + 256] = 0;
    __syncthreads();

    const float4* P4 = reinterpret_cast<const float4*>(
        pred + (size_t)b * NPRI * 6 + (size_t)seg * SEGBOX * 6);
    uint2* S2 = reinterpret_cast<uint2*>(g_score + (size_t)b * NPRI + seg * SEGBOX);

    #pragma unroll
    for (int it = 0; it < 4; it++) {
        int e = it * 256 + threadIdx.x;
        float4 a1 = P4[3 * e + 1];
        float4 a2 = P4[3 * e + 2];
        float s0 = fmaxf(a1.x, a1.y);
        float s1 = fmaxf(a2.z, a2.w);
        unsigned u0 = order_f((s0 > CONF_T) ? s0 : BIGNEG);
        unsigned u1 = order_f((s1 > CONF_T) ? s1 : BIGNEG);
        S2[e] = make_uint2(u0, u1);
        if (s0 > CONF_T) atomicAdd(&sh[min(511u, (u0 >> 18) - HBASE)], 1u);
        if (s1 > CONF_T) atomicAdd(&sh[min(511u, (u1 >> 18) - HBASE)], 1u);
    }
    __syncthreads();
    #pragma unroll
    for (int i = threadIdx.x; i < HBINS; i += 256) {
        unsigned v = sh[i];
        if (v) atomicAdd(&g_hist[b * HBINS + i], v);
    }
}

// ============ K3: threshold + gather + sort + NMS + emit =====================
__global__ __launch_bounds__(T3)
void k3_nms(const float* __restrict__ pred,
            const float* __restrict__ priors,
            float* __restrict__ out) {
    const int b    = blockIdx.x;
    const int tid  = threadIdx.x;
    const int lane = tid & 31;
    const int wid  = tid >> 5;
    const float* P = pred + (size_t)b * NPRI * 6;
    unsigned long long* cand = g_cand + (size_t)b * NPRI;

    __shared__ unsigned s_ss[HBINS];
    __shared__ unsigned long long s_top[512];
    __shared__ float s_x1[TOPK], s_y1[TOPK], s_x2[TOPK], s_y2[TOPK];
    __shared__ float s_ar[TOPK], s_sc[TOPK];
    __shared__ int   s_lab[TOPK];
    __shared__ unsigned s_sup[TOPK * WORDS];
    __shared__ unsigned s_keep[WORDS], s_act[WORDS];
    __shared__ int s_n, s_nkeep, s_krem, s_v;
    __shared__ unsigned long long s_pv;

    // ---- load + reset histogram ----
    if (tid < HBINS) {
        s_ss[tid] = g_hist[b * HBINS + tid];
        g_hist[b * HBINS + tid] = 0;
    }
    if (tid == 0) { s_n = 0; s_v = 0; }
    if (tid < WORDS) s_act[tid] = 0;
    __syncthreads();
    // suffix scan -> threshold bin
    for (int d = 1; d < HBINS; d <<= 1) {
        unsigned v = 0;
        if (tid < HBINS && tid + d < HBINS) v = s_ss[tid + d];
        __syncthreads();
        if (tid < HBINS) s_ss[tid] += v;
        __syncthreads();
    }
    if (tid < HBINS) {
        bool hit = (s_ss[tid] >= TOPK) && (tid == HBINS - 1 || s_ss[tid + 1] < TOPK);
        if (hit) s_v = tid;
    }
    __syncthreads();
    const unsigned thr = (HBASE + (unsigned)s_v) << 18;

    // ---- gather candidates ----
    {
        const uint4* S4 = reinterpret_cast<const uint4*>(g_score + (size_t)b * NPRI);
        #pragma unroll
        for (int k = 0; k < NPRI / (4 * T3); k++) {
            uint4 v = S4[k * T3 + tid];
            unsigned base_i = (unsigned)(k * T3 + tid) * 4u;
            #pragma unroll
            for (int e = 0; e < 4; e++) {
                unsigned u = (e == 0) ? v.x : (e == 1) ? v.y : (e == 2) ? v.z : v.w;
                bool p = (u >= thr);
                unsigned mask = __ballot_sync(0xffffffffu, p);
                if (mask) {
                    int leader = __ffs(mask) - 1;
                    int bp = 0;
                    if (lane == leader) bp = atomicAdd(&s_n, __popc(mask));
                    bp = __shfl_sync(0xffffffffu, bp, leader);
                    if (p) {
                        int off = bp + __popc(mask & ((1u << lane) - 1u));
                        if (off < NPRI)
                            cand[off] = ((unsigned long long)u << 32) |
                                        (0xFFFFFFFFu - (base_i + e));
                    }
                }
            }
        }
    }
    __syncthreads();
    const int cnt = s_n;

    if (cnt <= 512) {
        if (tid < 512) s_top[tid] = (tid < cnt) ? cand[tid] : 0ull;
        __syncthreads();
    } else {
        // exact radix-select of 400th-largest over cand[0..cnt)
        if (tid == 0) { s_pv = 0ull; s_krem = TOPK; }
        __syncthreads();
        for (int byt = 7; byt >= 0; --byt) {
            if (tid < 256) s_ss[tid] = 0;
            __syncthreads();
            unsigned long long pv = s_pv;
            unsigned long long hb =
                (byt == 7) ? 0ull : (0xFFFFFFFFFFFFFFFFull << ((byt + 1) * 8));
            for (int i = tid; i < cnt; i += T3) {
                unsigned long long e = cand[i];
                if (((e ^ pv) & hb) == 0)
                    atomicAdd(&s_ss[(unsigned)((e >> (byt * 8)) & 255)], 1u);
            }
            __syncthreads();
            if (tid == 0) {
                unsigned acc = 0; int d = 255;
                for (; d >= 0; --d) {
                    if (acc + s_ss[d] >= (unsigned)s_krem) break;
                    acc += s_ss[d];
                }
                s_krem -= (int)acc;
                s_pv |= ((unsigned long long)(unsigned)d) << (byt * 8);
            }
            __syncthreads();
        }
        unsigned long long kth = s_pv;
        if (tid == 0) s_n = 0;
        __syncthreads();
        for (int i = tid; i < cnt; i += T3) {
            unsigned long long e = cand[i];
            if (e >= kth) {
                int p = atomicAdd(&s_n, 1);
                if (p < 512) s_top[p] = e;
            }
        }
        __syncthreads();
        int n = s_n;
        if (tid < 512 && tid >= n) s_top[tid] = 0ull;
        __syncthreads();
    }

    // ---- bitonic sort 512 DESC ----
    for (int ksz = 2; ksz <= 512; ksz <<= 1)
        for (int j = ksz >> 1; j > 0; j >>= 1) {
            int ixj = tid ^ j;
            if (tid < 512 && ixj > tid) {
                unsigned long long a = s_top[tid], c = s_top[ixj];
                bool sw = ((tid & ksz) == 0) ? (a < c) : (a > c);
                if (sw) { s_top[tid] = c; s_top[ixj] = a; }
            }
            __syncthreads();
        }

    // ---- decode candidate boxes ----
    if (tid < TOPK) {
        unsigned long long key = s_top[tid];
        unsigned u = (unsigned)(key >> 32);
        float sc = unorder_f(u);
        unsigned idxu = 0xFFFFFFFFu - (unsigned)(key & 0xFFFFFFFFull);
        int idx = (int)min(idxu, (unsigned)(NPRI - 1));
        s_sc[tid] = sc;
        const float* pp = P + 6 * idx;
        float l0 = pp[0], l1 = pp[1], l2 = pp[2], l3 = pp[3];
        float c0 = pp[4], c1 = pp[5];
        float4 pr = *reinterpret_cast<const float4*>(priors + 4 * idx);
        float cx = __fadd_rn(pr.x, __fmul_rn(__fmul_rn(l0, 0.1f), pr.z));
        float cy = __fadd_rn(pr.y, __fmul_rn(__fmul_rn(l1, 0.1f), pr.w));
        float w  = __fmul_rn(pr.z, expf(__fmul_rn(l2, 0.2f)));
        float h  = __fmul_rn(pr.w, expf(__fmul_rn(l3, 0.2f)));
        float x1 = __fsub_rn(cx, __fmul_rn(w, 0.5f));
        float y1 = __fsub_rn(cy, __fmul_rn(h, 0.5f));
        float x2 = __fadd_rn(cx, __fmul_rn(w, 0.5f));
        float y2 = __fadd_rn(cy, __fmul_rn(h, 0.5f));
        s_x1[tid] = x1; s_y1[tid] = y1; s_x2[tid] = x2; s_y2[tid] = y2;
        s_ar[tid] = __fmul_rn(__fsub_rn(x2, x1), __fsub_rn(y2, y1));
        s_lab[tid] = (c1 > c0) ? 1 : 0;
    }
    __syncthreads();

    // ---- suppression bitmask: triangle-only, register j-boxes ----
    {
        // iteration space: (jb, i), jb in [0,WORDS), i in [0, min(400,(jb+1)*32))
        int g0   = wid * GPW;
        int gend = min(g0 + GPW, GTOT);
        if (g0 < gend) {
            int jb = 0, cum = 0;
            int len = 32;
            while (g0 >= cum + len) { cum += len; jb++; len = min(400, (jb + 1) * 32); }
            int j = jb * 32 + lane;
            bool jv = (j < TOPK);
            float jx1 = jv ? s_x1[j] : 0.f, jy1 = jv ? s_y1[j] : 0.f;
            float jx2 = jv ? s_x2[j] : 0.f, jy2 = jv ? s_y2[j] : 0.f;
            float jar = jv ? s_ar[j] : 0.f;
            for (int g = g0; g < gend; ++g) {
                int i = g - cum;
                if (i >= len) {
                    cum += len; jb++; len = min(400, (jb + 1) * 32);
                    i = 0;
                    j = jb * 32 + lane;
                    jv = (j < TOPK);
                    jx1 = jv ? s_x1[j] : 0.f; jy1 = jv ? s_y1[j] : 0.f;
                    jx2 = jv ? s_x2[j] : 0.f; jy2 = jv ? s_y2[j] : 0.f;
                    jar = jv ? s_ar[j] : 0.f;
                }
                float bx1 = s_x1[i], by1 = s_y1[i];
                float bx2 = s_x2[i], by2 = s_y2[i];
                float bar = s_ar[i];
                bool sbit = false;
                if (jv && j > i) {
                    float iw = fmaxf(__fsub_rn(fminf(jx2, bx2), fmaxf(jx1, bx1)), 0.0f);
                    float ih = fmaxf(__fsub_rn(fminf(jy2, by2), fmaxf(jy1, by1)), 0.0f);
                    float inter = __fmul_rn(iw, ih);
                    float den = __fadd_rn(__fsub_rn(__fadd_rn(bar, jar), inter), 1e-12f);
                    sbit = (__fdiv_rn(inter, den) > NMS_T);
                }
                unsigned wd = __ballot_sync(0xffffffffu, sbit);
                if (lane == 0) {
                    s_sup[i * WORDS + jb] = wd;
                    if (wd) atomicOr(&s_act[i >> 5], 1u << (i & 31));
                }
            }
        } else {
            // keep warp convergent for ballots elsewhere (no-op)
        }
    }
    if (tid < WORDS * 32) {
        bool v = (tid < TOPK) && (s_sc[tid] > CONF_T);
        unsigned m = __ballot_sync(0xffffffffu, v);
        if (lane == 0) s_keep[wid] = m;
    }
    __syncthreads();

    // ---- greedy NMS: visit only kept rows that suppress something ----
    if (tid == 0) {
        unsigned kp[WORDS], rem[WORDS];
        #pragma unroll
        for (int w = 0; w < WORDS; w++) {
            kp[w] = s_keep[w];
            rem[w] = kp[w] & s_act[w];
        }
        for (;;) {
            int i = -1;
            #pragma unroll
            for (int w = 0; w < WORDS; w++)
                if (i < 0 && rem[w]) i = (w << 5) + (__ffs(rem[w]) - 1);
            if (i < 0) break;
            rem[i >> 5] &= rem[i >> 5] - 1;     // clear lowest set bit (= i)
            const unsigned* row = &s_sup[i * WORDS];
            for (int w = i >> 5; w < WORDS; w++) {
                unsigned s = row[w];
                kp[w] &= ~s;
                rem[w] &= ~s;
            }
        }
        int nk = 0;
        #pragma unroll
        for (int w = 0; w < WORDS; w++) { s_keep[w] = kp[w]; nk += __popc(kp[w]); }
        s_nkeep = nk;
    }
    __syncthreads();

    // ---- stable ascending sort of kept ----
    if (tid < 512) {
        int i = tid;
        unsigned long long key2 = ~0ull;
        bool kept = (i < TOPK) && ((s_keep[i >> 5] >> (i & 31)) & 1u);
        if (kept) {
            unsigned u = order_f(s_sc[i]);
            key2 = ((unsigned long long)u << 32) | (unsigned)i;
        }
        s_top[i] = key2;
    }
    __syncthreads();
    for (int ksz = 2; ksz <= 512; ksz <<= 1)
        for (int j = ksz >> 1; j > 0; j >>= 1) {
            int ixj = tid ^ j;
            if (tid < 512 && ixj > tid) {
                unsigned long long a = s_top[tid], c = s_top[ixj];
                bool sw = ((tid & ksz) == 0) ? (a > c) : (a < c);
                if (sw) { s_top[tid] = c; s_top[ixj] = a; }
            }
            __syncthreads();
        }

    // ---- emit ----
    {
        float* ob = out + (size_t)b * (KEEPK * 6);
        int nk = min(s_nkeep, KEEPK);
        if (tid < KEEPK) {
            int r = tid;
            float o0 = 0.f, o1 = 0.f, o2 = 0.f, o3 = 0.f, o4 = 0.f, o5 = 0.f;
            if (r < nk) {
                int pos = (int)(s_top[r] & 0xFFFFFFFFull);
                o0 = (float)s_lab[pos];
                o1 = s_sc[pos];
                o2 = s_x1[pos]; o3 = s_y1[pos];
                o4 = s_x2[pos]; o5 = s_y2[pos];
            }
            ob[r * 6 + 0] = o0; ob[r * 6 + 1] = o1; ob[r * 6 + 2] = o2;
            ob[r * 6 + 3] = o3; ob[r * 6 + 4] = o4; ob[r * 6 + 5] = o5;
        }
    }
}

extern "C" void kernel_launch(void* const* d_in, const int* in_sizes, int n_in,
                              void* d_out, int out_size) {
    const float* pred   = (const float*)d_in[0];
    const float* priors = (const float*)d_in[1];
    int nb = in_sizes[0] / (NPRI * 6);
    if (nb <= 0 || nb > NB) nb = NB;
    k1_score<<<nb * SEGS, 256>>>(pred);
    k3_nms<<<nb, T3>>>(pred, priors, (float*)d_out);
}

// round 9
// speedup vs baseline: 1.0412x; 1.0412x over previous
#include <cuda_runtime.h>
#include <cstdint>

#define NB    128
#define NPRI  32768
#define TOPK  400
#define KEEPK 200
#define T3    1024
#define WORDS 13
#define CONF_T 0.5f
#define NMS_T  0.5f
#define BIGNEG -1000000000.0f
#define HBINS 512
#define HBASE 12224u          // order_f(0.5) >> 18
#define SEGS  16
#define SEGBOX (NPRI / SEGS)
#define GTOT  2896            // sum_{jb=0..12} min(400,(jb+1)*32)
#define GPW   91              // ceil(GTOT/32)

__device__ unsigned           g_score[NB * NPRI];
__device__ unsigned long long g_cand[NB * NPRI];
__device__ unsigned           g_hist[NB * HBINS];

__device__ __forceinline__ unsigned order_f(float f) {
    unsigned u = __float_as_uint(f);
    return (u & 0x80000000u) ? ~u : (u | 0x80000000u);
}
__device__ __forceinline__ float unorder_f(unsigned u) {
    unsigned v = (u & 0x80000000u) ? (u ^ 0x80000000u) : ~u;
    return __uint_as_float(v);
}

// ============ K1: stream pred, emit ordered scores + 512-bin histogram ======
__global__ __launch_bounds__(256)
void k1_score(const float* __restrict__ pred) {
    const int b   = blockIdx.x >> 4;
    const int seg = blockIdx.x & 15;
    __shared__ unsigned sh[HBINS];
    sh[threadIdx.x] = 0; sh[threadIdx.x + 256] = 0;
    __syncthreads();

    const float4* P4 = reinterpret_cast<const float4*>(
        pred + (size_t)b * NPRI * 6 + (size_t)seg * SEGBOX * 6);
    uint2* S2 = reinterpret_cast<uint2*>(g_score + (size_t)b * NPRI + seg * SEGBOX);

    #pragma unroll
    for (int it = 0; it < 4; it++) {
        int e = it * 256 + threadIdx.x;
        float4 a1 = P4[3 * e + 1];
        float4 a2 = P4[3 * e + 2];
        float s0 = fmaxf(a1.x, a1.y);
        float s1 = fmaxf(a2.z, a2.w);
        unsigned u0 = order_f((s0 > CONF_T) ? s0 : BIGNEG);
        unsigned u1 = order_f((s1 > CONF_T) ? s1 : BIGNEG);
        S2[e] = make_uint2(u0, u1);
        if (s0 > CONF_T) atomicAdd(&sh[min(511u, (u0 >> 18) - HBASE)], 1u);
        if (s1 > CONF_T) atomicAdd(&sh[min(511u, (u1 >> 18) - HBASE)], 1u);
    }
    __syncthreads();
    #pragma unroll
    for (int i = threadIdx.x; i < HBINS; i += 256) {
        unsigned v = sh[i];
        if (v) atomicAdd(&g_hist[b * HBINS + i], v);
    }
}

// ============ K3: threshold + gather + sort + NMS + emit =====================
__global__ __launch_bounds__(T3)
void k3_nms(const float* __restrict__ pred,
            const float* __restrict__ priors,
            float* __restrict__ out) {
    const int b    = blockIdx.x;
    const int tid  = threadIdx.x;
    const int lane = tid & 31;
    const int wid  = tid >> 5;
    const float* P = pred + (size_t)b * NPRI * 6;
    unsigned long long* cand = g_cand + (size_t)b * NPRI;

    __shared__ unsigned s_ss[HBINS];
    __shared__ unsigned long long s_cand[512];
    __shared__ unsigned long long s_top[512];
    __shared__ float s_x1[TOPK], s_y1[TOPK], s_x2[TOPK], s_y2[TOPK];
    __shared__ float s_ar[TOPK], s_sc[TOPK];
    __shared__ int   s_lab[TOPK];
    __shared__ unsigned s_sup[TOPK * WORDS];
    __shared__ unsigned s_keep[WORDS], s_act[WORDS];
    __shared__ int s_n, s_nkeep, s_krem, s_v;
    __shared__ unsigned long long s_pv;

    // ---- load + reset histogram ----
    if (tid < HBINS) {
        s_ss[tid] = g_hist[b * HBINS + tid];
        g_hist[b * HBINS + tid] = 0;
    }
    if (tid == 0) { s_n = 0; s_v = 0; }
    if (tid < WORDS) s_act[tid] = 0;
    __syncthreads();
    // suffix scan -> threshold bin
    for (int d = 1; d < HBINS; d <<= 1) {
        unsigned v = 0;
        if (tid < HBINS && tid + d < HBINS) v = s_ss[tid + d];
        __syncthreads();
        if (tid < HBINS) s_ss[tid] += v;
        __syncthreads();
    }
    if (tid < HBINS) {
        bool hit = (s_ss[tid] >= TOPK) && (tid == HBINS - 1 || s_ss[tid + 1] < TOPK);
        if (hit) s_v = tid;
    }
    __syncthreads();
    const unsigned thr = (HBASE + (unsigned)s_v) << 18;

    // ---- gather candidates: predicated append, shared staging ----
    {
        const uint4* S4 = reinterpret_cast<const uint4*>(g_score + (size_t)b * NPRI);
        #pragma unroll
        for (int k0 = 0; k0 < 8; k0 += 4) {
            uint4 v[4];
            #pragma unroll
            for (int t = 0; t < 4; t++) v[t] = S4[(k0 + t) * T3 + tid];
            #pragma unroll
            for (int t = 0; t < 4; t++) {
                unsigned base_i = (unsigned)((k0 + t) * T3 + tid) * 4u;
                #pragma unroll
                for (int e = 0; e < 4; e++) {
                    unsigned u = (e == 0) ? v[t].x : (e == 1) ? v[t].y :
                                 (e == 2) ? v[t].z : v[t].w;
                    if (u >= thr) {
                        int off = atomicAdd(&s_n, 1);
                        unsigned long long key =
                            ((unsigned long long)u << 32) |
                            (0xFFFFFFFFu - (base_i + e));
                        cand[off] = key;                 // for rare fallback
                        if (off < 512) s_cand[off] = key;
                    }
                }
            }
        }
    }
    __syncthreads();
    const int cnt = s_n;

    if (cnt <= 512) {
        if (tid < 512) s_top[tid] = (tid < cnt) ? s_cand[tid] : 0ull;
        __syncthreads();
    } else {
        // exact radix-select of 400th-largest over cand[0..cnt)
        if (tid == 0) { s_pv = 0ull; s_krem = TOPK; }
        __syncthreads();
        for (int byt = 7; byt >= 0; --byt) {
            if (tid < 256) s_ss[tid] = 0;
            __syncthreads();
            unsigned long long pv = s_pv;
            unsigned long long hb =
                (byt == 7) ? 0ull : (0xFFFFFFFFFFFFFFFFull << ((byt + 1) * 8));
            for (int i = tid; i < cnt; i += T3) {
                unsigned long long e = cand[i];
                if (((e ^ pv) & hb) == 0)
                    atomicAdd(&s_ss[(unsigned)((e >> (byt * 8)) & 255)], 1u);
            }
            __syncthreads();
            if (tid == 0) {
                unsigned acc = 0; int d = 255;
                for (; d >= 0; --d) {
                    if (acc + s_ss[d] >= (unsigned)s_krem) break;
                    acc += s_ss[d];
                }
                s_krem -= (int)acc;
                s_pv |= ((unsigned long long)(unsigned)d) << (byt * 8);
            }
            __syncthreads();
        }
        unsigned long long kth = s_pv;
        if (tid == 0) s_n = 0;
        __syncthreads();
        for (int i = tid; i < cnt; i += T3) {
            unsigned long long e = cand[i];
            if (e >= kth) {
                int p = atomicAdd(&s_n, 1);
                if (p < 512) s_top[p] = e;
            }
        }
        __syncthreads();
        int n = s_n;
        if (tid < 512 && tid >= n) s_top[tid] = 0ull;
        __syncthreads();
    }

    // ---- bitonic sort 512 DESC ----
    for (int ksz = 2; ksz <= 512; ksz <<= 1)
        for (int j = ksz >> 1; j > 0; j >>= 1) {
            int ixj = tid ^ j;
            if (tid < 512 && ixj > tid) {
                unsigned long long a = s_top[tid], c = s_top[ixj];
                bool sw = ((tid & ksz) == 0) ? (a < c) : (a > c);
                if (sw) { s_top[tid] = c; s_top[ixj] = a; }
            }
            __syncthreads();
        }

    // ---- decode candidate boxes ----
    if (tid < TOPK) {
        unsigned long long key = s_top[tid];
        unsigned u = (unsigned)(key >> 32);
        float sc = unorder_f(u);
        unsigned idxu = 0xFFFFFFFFu - (unsigned)(key & 0xFFFFFFFFull);
        int idx = (int)min(idxu, (unsigned)(NPRI - 1));
        s_sc[tid] = sc;
        const float* pp = P + 6 * idx;
        float l0 = pp[0], l1 = pp[1], l2 = pp[2], l3 = pp[3];
        float c0 = pp[4], c1 = pp[5];
        float4 pr = *reinterpret_cast<const float4*>(priors + 4 * idx);
        float cx = __fadd_rn(pr.x, __fmul_rn(__fmul_rn(l0, 0.1f), pr.z));
        float cy = __fadd_rn(pr.y, __fmul_rn(__fmul_rn(l1, 0.1f), pr.w));
        float w  = __fmul_rn(pr.z, expf(__fmul_rn(l2, 0.2f)));
        float h  = __fmul_rn(pr.w, expf(__fmul_rn(l3, 0.2f)));
        float x1 = __fsub_rn(cx, __fmul_rn(w, 0.5f));
        float y1 = __fsub_rn(cy, __fmul_rn(h, 0.5f));
        float x2 = __fadd_rn(cx, __fmul_rn(w, 0.5f));
        float y2 = __fadd_rn(cy, __fmul_rn(h, 0.5f));
        s_x1[tid] = x1; s_y1[tid] = y1; s_x2[tid] = x2; s_y2[tid] = y2;
        s_ar[tid] = __fmul_rn(__fsub_rn(x2, x1), __fsub_rn(y2, y1));
        s_lab[tid] = (c1 > c0) ? 1 : 0;
    }
    __syncthreads();

    // ---- suppression bitmask: triangle-only, register j-boxes ----
    {
        int g0   = wid * GPW;
        int gend = min(g0 + GPW, GTOT);
        if (g0 < gend) {
            int jb = 0, cum = 0;
            int len = 32;
            while (g0 >= cum + len) { cum += len; jb++; len = min(400, (jb + 1) * 32); }
            int j = jb * 32 + lane;
            bool jv = (j < TOPK);
            float jx1 = jv ? s_x1[j] : 0.f, jy1 = jv ? s_y1[j] : 0.f;
            float jx2 = jv ? s_x2[j] : 0.f, jy2 = jv ? s_y2[j] : 0.f;
            float jar = jv ? s_ar[j] : 0.f;
            for (int g = g0; g < gend; ++g) {
                int i = g - cum;
                if (i >= len) {
                    cum += len; jb++; len = min(400, (jb + 1) * 32);
                    i = 0;
                    j = jb * 32 + lane;
                    jv = (j < TOPK);
                    jx1 = jv ? s_x1[j] : 0.f; jy1 = jv ? s_y1[j] : 0.f;
                    jx2 = jv ? s_x2[j] : 0.f; jy2 = jv ? s_y2[j] : 0.f;
                    jar = jv ? s_ar[j] : 0.f;
                }
                float bx1 = s_x1[i], by1 = s_y1[i];
                float bx2 = s_x2[i], by2 = s_y2[i];
                float bar = s_ar[i];
                bool sbit = false;
                if (jv && j > i) {
                    float iw = fmaxf(__fsub_rn(fminf(jx2, bx2), fmaxf(jx1, bx1)), 0.0f);
                    float ih = fmaxf(__fsub_rn(fminf(jy2, by2), fmaxf(jy1, by1)), 0.0f);
                    float inter = __fmul_rn(iw, ih);
                    float den = __fadd_rn(__fsub_rn(__fadd_rn(bar, jar), inter), 1e-12f);
                    sbit = (__fdiv_rn(inter, den) > NMS_T);
                }
                unsigned wd = __ballot_sync(0xffffffffu, sbit);
                if (lane == 0) {
                    s_sup[i * WORDS + jb] = wd;
                    if (wd) atomicOr(&s_act[i >> 5], 1u << (i & 31));
                }
            }
        }
    }
    if (tid < WORDS * 32) {
        bool v = (tid < TOPK) && (s_sc[tid] > CONF_T);
        unsigned m = __ballot_sync(0xffffffffu, v);
        if (lane == 0) s_keep[wid] = m;
    }
    __syncthreads();

    // ---- greedy NMS: visit only kept rows that suppress something ----
    if (tid == 0) {
        unsigned kp[WORDS], rem[WORDS];
        #pragma unroll
        for (int w = 0; w < WORDS; w++) {
            kp[w] = s_keep[w];
            rem[w] = kp[w] & s_act[w];
        }
        for (;;) {
            int i = -1;
            #pragma unroll
            for (int w = 0; w < WORDS; w++)
                if (i < 0 && rem[w]) i = (w << 5) + (__ffs(rem[w]) - 1);
            if (i < 0) break;
            rem[i >> 5] &= rem[i >> 5] - 1;
            const unsigned* row = &s_sup[i * WORDS];
            for (int w = i >> 5; w < WORDS; w++) {
                unsigned s = row[w];
                kp[w] &= ~s;
                rem[w] &= ~s;
            }
        }
        int nk = 0;
        #pragma unroll
        for (int w = 0; w < WORDS; w++) { s_keep[w] = kp[w]; nk += __popc(kp[w]); }
        s_nkeep = nk;
    }
    __syncthreads();

    // ---- direct rank computation + emit (replaces second bitonic sort) ----
    // Candidates are DESC by score (ties: prior-idx asc). Ascending stable rank:
    //   r = (nkeep - run_end) + (p - run_start)
    // where p = #kept j<i, run = kept elements with equal score around i.
    {
        float* ob = out + (size_t)b * (KEEPK * 6);
        const int nkeep = s_nkeep;
        const int nk = min(nkeep, KEEPK);
        // zero-fill rows [nk, KEEPK)
        if (tid >= nk && tid < KEEPK) {
            #pragma unroll
            for (int q = 0; q < 6; q++) ob[tid * 6 + q] = 0.0f;
        }
        if (tid < TOPK) {
            bool kept = (s_keep[tid >> 5] >> (tid & 31)) & 1u;
            if (kept) {
                float sc = s_sc[tid];
                int p = 0;
                int wi = tid >> 5;
                for (int w = 0; w < wi; w++) p += __popc(s_keep[w]);
                p += __popc(s_keep[wi] & ((1u << (tid & 31)) - 1u));
                int sct = 0;   // kept equal-score elements before me
                for (int j = tid - 1; j >= 0 && s_sc[j] == sc; --j)
                    if ((s_keep[j >> 5] >> (j & 31)) & 1u) sct++;
                int ect = 0;   // kept equal-score elements after me
                for (int j = tid + 1; j < TOPK && s_sc[j] == sc; ++j)
                    if ((s_keep[j >> 5] >> (j & 31)) & 1u) ect++;
                int r = (nkeep - (p + ect + 1)) + sct;
                if (r < KEEPK) {
                    ob[r * 6 + 0] = (float)s_lab[tid];
                    ob[r * 6 + 1] = sc;
                    ob[r * 6 + 2] = s_x1[tid];
                    ob[r * 6 + 3] = s_y1[tid];
                    ob[r * 6 + 4] = s_x2[tid];
                    ob[r * 6 + 5] = s_y2[tid];
                }
            }
        }
    }
}

extern "C" void kernel_launch(void* const* d_in, const int* in_sizes, int n_in,
                              void* d_out, int out_size) {
    const float* pred   = (const float*)d_in[0];
    const float* priors = (const float*)d_in[1];
    int nb = in_sizes[0] / (NPRI * 6);
    if (nb <= 0 || nb > NB) nb = NB;
    k1_score<<<nb * SEGS, 256>>>(pred);
    k3_nms<<<nb, T3>>>(pred, priors, (float*)d_out);
}

// round 11
// speedup vs baseline: 1.6921x; 1.6252x over previous
#include <cuda_runtime.h>
#include <cstdint>

#define NB    128
#define NPRI  32768
#define TOPK  400
#define KEEPK 200
#define WORDS 13
#define CONF_T 0.5f
#define NMS_T  0.5f
#define BIGNEG -1000000000.0f
#define HBINS 512
#define HBASE 12224u          // order_f(0.5) >> 18
#define SEGS  16
#define SEGBOX (NPRI / SEGS)

__device__ unsigned           g_score[NB * NPRI];
__device__ unsigned long long g_cand[NB * NPRI];   // fallback only
__device__ unsigned           g_hist[NB * HBINS];
__device__ float4             g_box4[NB * TOPK];   // x1,y1,x2,y2
__device__ float4             g_aux[NB * TOPK];    // area, score, label, 0
__device__ unsigned           g_sup[NB * TOPK * WORDS];

__device__ __forceinline__ unsigned order_f(float f) {
    unsigned u = __float_as_uint(f);
    return (u & 0x80000000u) ? ~u : (u | 0x80000000u);
}
__device__ __forceinline__ float unorder_f(unsigned u) {
    unsigned v = (u & 0x80000000u) ? (u ^ 0x80000000u) : ~u;
    return __uint_as_float(v);
}

// ============ K1: stream pred, emit ordered scores + 512-bin histogram ======
__global__ __launch_bounds__(256)
void k1_score(const float* __restrict__ pred) {
    const int b   = blockIdx.x >> 4;
    const int seg = blockIdx.x & 15;
    __shared__ unsigned sh[HBINS];
    sh[threadIdx.x] = 0; sh[threadIdx.x + 256] = 0;
    __syncthreads();

    const float4* P4 = reinterpret_cast<const float4*>(
        pred + (size_t)b * NPRI * 6 + (size_t)seg * SEGBOX * 6);
    uint2* S2 = reinterpret_cast<uint2*>(g_score + (size_t)b * NPRI + seg * SEGBOX);

    #pragma unroll
    for (int it = 0; it < 4; it++) {
        int e = it * 256 + threadIdx.x;
        float4 a1 = P4[3 * e + 1];
        float4 a2 = P4[3 * e + 2];
        float s0 = fmaxf(a1.x, a1.y);
        float s1 = fmaxf(a2.z, a2.w);
        unsigned u0 = order_f((s0 > CONF_T) ? s0 : BIGNEG);
        unsigned u1 = order_f((s1 > CONF_T) ? s1 : BIGNEG);
        S2[e] = make_uint2(u0, u1);
        if (s0 > CONF_T) atomicAdd(&sh[min(511u, (u0 >> 18) - HBASE)], 1u);
        if (s1 > CONF_T) atomicAdd(&sh[min(511u, (u1 >> 18) - HBASE)], 1u);
    }
    __syncthreads();
    #pragma unroll
    for (int i = threadIdx.x; i < HBINS; i += 256) {
        unsigned v = sh[i];
        if (v) atomicAdd(&g_hist[b * HBINS + i], v);
    }
}

// ============ K2: threshold + gather + sort + decode -> box records =========
__global__ __launch_bounds__(512)
void k2_select(const float* __restrict__ pred,
               const float* __restrict__ priors) {
    const int b   = blockIdx.x;
    const int tid = threadIdx.x;
    const float* P = pred + (size_t)b * NPRI * 6;
    unsigned long long* cand = g_cand + (size_t)b * NPRI;

    __shared__ unsigned s_ss[HBINS];
    __shared__ unsigned long long s_cand[512];
    __shared__ unsigned long long s_top[512];
    __shared__ int s_n, s_krem, s_v;
    __shared__ unsigned long long s_pv;

    // hist load + reset + suffix scan
    s_ss[tid] = g_hist[b * HBINS + tid];
    g_hist[b * HBINS + tid] = 0;
    if (tid == 0) { s_n = 0; s_v = 0; }
    __syncthreads();
    for (int d = 1; d < HBINS; d <<= 1) {
        unsigned v = (tid + d < HBINS) ? s_ss[tid + d] : 0u;
        __syncthreads();
        s_ss[tid] += v;
        __syncthreads();
    }
    {
        bool hit = (s_ss[tid] >= TOPK) && (tid == HBINS - 1 || s_ss[tid + 1] < TOPK);
        if (hit) s_v = tid;
    }
    __syncthreads();
    const unsigned thr = (HBASE + (unsigned)s_v) << 18;

    // gather: predicated append
    {
        const uint4* S4 = reinterpret_cast<const uint4*>(g_score + (size_t)b * NPRI);
        #pragma unroll
        for (int k0 = 0; k0 < 16; k0 += 4) {
            uint4 v[4];
            #pragma unroll
            for (int t = 0; t < 4; t++) v[t] = S4[(k0 + t) * 512 + tid];
            #pragma unroll
            for (int t = 0; t < 4; t++) {
                unsigned base_i = (unsigned)((k0 + t) * 512 + tid) * 4u;
                #pragma unroll
                for (int e = 0; e < 4; e++) {
                    unsigned u = (e == 0) ? v[t].x : (e == 1) ? v[t].y :
                                 (e == 2) ? v[t].z : v[t].w;
                    if (u >= thr) {
                        int off = atomicAdd(&s_n, 1);
                        unsigned long long key =
                            ((unsigned long long)u << 32) |
                            (0xFFFFFFFFu - (base_i + e));
                        cand[off] = key;
                        if (off < 512) s_cand[off] = key;
                    }
                }
            }
        }
    }
    __syncthreads();
    const int cnt = s_n;

    if (cnt <= 512) {
        s_top[tid] = (tid < cnt) ? s_cand[tid] : 0ull;
        __syncthreads();
    } else {
        // exact radix-select fallback
        if (tid == 0) { s_pv = 0ull; s_krem = TOPK; }
        __syncthreads();
        for (int byt = 7; byt >= 0; --byt) {
            if (tid < 256) s_ss[tid] = 0;
            __syncthreads();
            unsigned long long pv = s_pv;
            unsigned long long hb =
                (byt == 7) ? 0ull : (0xFFFFFFFFFFFFFFFFull << ((byt + 1) * 8));
            for (int i = tid; i < cnt; i += 512) {
                unsigned long long e = cand[i];
                if (((e ^ pv) & hb) == 0)
                    atomicAdd(&s_ss[(unsigned)((e >> (byt * 8)) & 255)], 1u);
            }
            __syncthreads();
            if (tid == 0) {
                unsigned acc = 0; int d = 255;
                for (; d >= 0; --d) {
                    if (acc + s_ss[d] >= (unsigned)s_krem) break;
                    acc += s_ss[d];
                }
                s_krem -= (int)acc;
                s_pv |= ((unsigned long long)(unsigned)d) << (byt * 8);
            }
            __syncthreads();
        }
        unsigned long long kth = s_pv;
        if (tid == 0) s_n = 0;
        __syncthreads();
        for (int i = tid; i < cnt; i += 512) {
            unsigned long long e = cand[i];
            if (e >= kth) {
                int p = atomicAdd(&s_n, 1);
                if (p < 512) s_top[p] = e;
            }
        }
        __syncthreads();
        int n = s_n;
        if (tid >= n) s_top[tid] = 0ull;
        __syncthreads();
    }

    // bitonic sort 512 DESC
    for (int ksz = 2; ksz <= 512; ksz <<= 1)
        for (int j = ksz >> 1; j > 0; j >>= 1) {
            int ixj = tid ^ j;
            if (ixj > tid) {
                unsigned long long a = s_top[tid], c = s_top[ixj];
                bool sw = ((tid & ksz) == 0) ? (a < c) : (a > c);
                if (sw) { s_top[tid] = c; s_top[ixj] = a; }
            }
            __syncthreads();
        }

    // decode + store records
    if (tid < TOPK) {
        unsigned long long key = s_top[tid];
        unsigned u = (unsigned)(key >> 32);
        float sc = unorder_f(u);
        unsigned idxu = 0xFFFFFFFFu - (unsigned)(key & 0xFFFFFFFFull);
        int idx = (int)min(idxu, (unsigned)(NPRI - 1));
        const float* pp = P + 6 * idx;
        float l0 = pp[0], l1 = pp[1], l2 = pp[2], l3 = pp[3];
        float c0 = pp[4], c1 = pp[5];
        float4 pr = *reinterpret_cast<const float4*>(priors + 4 * idx);
        float cx = __fadd_rn(pr.x, __fmul_rn(__fmul_rn(l0, 0.1f), pr.z));
        float cy = __fadd_rn(pr.y, __fmul_rn(__fmul_rn(l1, 0.1f), pr.w));
        float w  = __fmul_rn(pr.z, expf(__fmul_rn(l2, 0.2f)));
        float h  = __fmul_rn(pr.w, expf(__fmul_rn(l3, 0.2f)));
        float x1 = __fsub_rn(cx, __fmul_rn(w, 0.5f));
        float y1 = __fsub_rn(cy, __fmul_rn(h, 0.5f));
        float x2 = __fadd_rn(cx, __fmul_rn(w, 0.5f));
        float y2 = __fadd_rn(cy, __fmul_rn(h, 0.5f));
        float ar = __fmul_rn(__fsub_rn(x2, x1), __fsub_rn(y2, y1));
        g_box4[b * TOPK + tid] = make_float4(x1, y1, x2, y2);
        g_aux[b * TOPK + tid]  = make_float4(ar, sc, (c1 > c0) ? 1.0f : 0.0f, 0.0f);
    }
}

// ============ K3b: suppression masks, one 32-wide j-column per block ========
__global__ __launch_bounds__(256)
void k3b_mask() {
    const int jb = blockIdx.x;            // 0..12
    const int b  = blockIdx.y;
    const int lane = threadIdx.x & 31;
    const int wid  = threadIdx.x >> 5;    // 0..7

    __shared__ float s_x1[TOPK], s_y1[TOPK], s_x2[TOPK], s_y2[TOPK], s_ar[TOPK];
    for (int i = threadIdx.x; i < TOPK; i += 256) {
        float4 bb = g_box4[b * TOPK + i];
        s_x1[i] = bb.x; s_y1[i] = bb.y; s_x2[i] = bb.z; s_y2[i] = bb.w;
        s_ar[i] = g_aux[b * TOPK + i].x;
    }
    __syncthreads();

    int j = jb * 32 + lane;
    bool jv = (j < TOPK);
    float jx1 = jv ? s_x1[j] : 0.f, jy1 = jv ? s_y1[j] : 0.f;
    float jx2 = jv ? s_x2[j] : 0.f, jy2 = jv ? s_y2[j] : 0.f;
    float jar = jv ? s_ar[j] : 0.f;

    const int rows = min(TOPK, (jb + 1) * 32);
    unsigned* outw = g_sup + ((size_t)b * TOPK) * WORDS;
    for (int i = wid; i < rows; i += 8) {
        float bx1 = s_x1[i], by1 = s_y1[i];
        float bx2 = s_x2[i], by2 = s_y2[i];
        float bar = s_ar[i];
        bool sbit = false;
        if (jv && j > i) {
            float iw = fmaxf(__fsub_rn(fminf(jx2, bx2), fmaxf(jx1, bx1)), 0.0f);
            float ih = fmaxf(__fsub_rn(fminf(jy2, by2), fmaxf(jy1, by1)), 0.0f);
            float inter = __fmul_rn(iw, ih);
            float den = __fadd_rn(__fsub_rn(__fadd_rn(bar, jar), inter), 1e-12f);
            sbit = (__fdiv_rn(inter, den) > NMS_T);
        }
        unsigned wd = __ballot_sync(0xffffffffu, sbit);
        if (lane == 0) outw[i * WORDS + jb] = wd;
    }
}

// ============ K3c: greedy NMS + rank + emit =================================
__global__ __launch_bounds__(512)
void k3c_final(float* __restrict__ out) {
    const int b    = blockIdx.x;
    const int tid  = threadIdx.x;
    const int lane = tid & 31;
    const int wid  = tid >> 5;

    __shared__ unsigned s_sup[TOPK * WORDS];
    __shared__ float s_x1[TOPK], s_y1[TOPK], s_x2[TOPK], s_y2[TOPK];
    __shared__ float s_sc[TOPK], s_lab[TOPK];
    __shared__ unsigned s_keep[WORDS], s_act[WORDS];
    __shared__ int s_nkeep;

    const unsigned* supg = g_sup + ((size_t)b * TOPK) * WORDS;
    for (int i = tid; i < TOPK * WORDS; i += 512) s_sup[i] = supg[i];
    for (int i = tid; i < TOPK; i += 512) {
        float4 bb = g_box4[b * TOPK + i];
        s_x1[i] = bb.x; s_y1[i] = bb.y; s_x2[i] = bb.z; s_y2[i] = bb.w;
        float4 ax = g_aux[b * TOPK + i];
        s_sc[i] = ax.y; s_lab[i] = ax.z;
    }
    __syncthreads();

    // keep init + activity bits (warps 0..12 fully covered by tid<416)
    if (tid < WORDS * 32) {
        bool a = false;
        if (tid < TOPK) {
            unsigned o = 0;
            for (int w = tid >> 5; w < WORDS; w++) o |= s_sup[tid * WORDS + w];
            a = (o != 0);
        }
        unsigned ma = __ballot_sync(0xffffffffu, a);
        bool v = (tid < TOPK) && (s_sc[tid] > CONF_T);
        unsigned mk = __ballot_sync(0xffffffffu, v);
        if (lane == 0) { s_act[wid] = ma; s_keep[wid] = mk; }
    }
    __syncthreads();

    // greedy: warp 0, lane w owns word w
    if (wid == 0) {
        unsigned kp = (lane < WORDS) ? s_keep[lane] : 0u;
        unsigned rm = (lane < WORDS) ? (kp & s_act[lane]) : 0u;
        for (;;) {
            int cnd = rm ? (lane * 32 + __ffs(rm) - 1) : 0x7FFFFFFF;
            int i = (int)__reduce_min_sync(0xffffffffu, (unsigned)cnd);
            if (i == 0x7FFFFFFF) break;
            if (lane == (i >> 5)) rm &= ~(1u << (i & 31));
            unsigned s = (lane < WORDS && lane >= (i >> 5))
                         ? s_sup[i * WORDS + lane] : 0u;
            kp &= ~s; rm &= ~s;
        }
        if (lane < WORDS) s_keep[lane] = kp;
        int nk = __popc(kp);
        #pragma unroll
        for (int d = 16; d; d >>= 1) nk += __shfl_xor_sync(0xffffffffu, nk, d);
        if (lane == 0) s_nkeep = nk;
    }
    __syncthreads();

    // rank + emit
    {
        float* ob = out + (size_t)b * (KEEPK * 6);
        const int nkeep = s_nkeep;
        const int nk = min(nkeep, KEEPK);
        if (tid >= nk && tid < KEEPK) {
            #pragma unroll
            for (int q = 0; q < 6; q++) ob[tid * 6 + q] = 0.0f;
        }
        if (tid < TOPK) {
            bool kept = (s_keep[tid >> 5] >> (tid & 31)) & 1u;
            if (kept) {
                float sc = s_sc[tid];
                int p = 0;
                int wi = tid >> 5;
                for (int w = 0; w < wi; w++) p += __popc(s_keep[w]);
                p += __popc(s_keep[wi] & ((1u << (tid & 31)) - 1u));
                int sct = 0;
                for (int j = tid - 1; j >= 0 && s_sc[j] == sc; --j)
                    if ((s_keep[j >> 5] >> (j & 31)) & 1u) sct++;
                int ect = 0;
                for (int j = tid + 1; j < TOPK && s_sc[j] == sc; ++j)
                    if ((s_keep[j >> 5] >> (j & 31)) & 1u) ect++;
                int r = (nkeep - (p + ect + 1)) + sct;
                if (r < KEEPK) {
                    ob[r * 6 + 0] = s_lab[tid];
                    ob[r * 6 + 1] = sc;
                    ob[r * 6 + 2] = s_x1[tid];
                    ob[r * 6 + 3] = s_y1[tid];
                    ob[r * 6 + 4] = s_x2[tid];
                    ob[r * 6 + 5] = s_y2[tid];
                }
            }
        }
    }
}

extern "C" void kernel_launch(void* const* d_in, const int* in_sizes, int n_in,
                              void* d_out, int out_size) {
    const float* pred   = (const float*)d_in[0];
    const float* priors = (const float*)d_in[1];
    int nb = in_sizes[0] / (NPRI * 6);
    if (nb <= 0 || nb > NB) nb = NB;
    k1_score<<<nb * SEGS, 256>>>(pred);
    k2_select<<<nb, 512>>>(pred, priors);
    k3b_mask<<<dim3(WORDS, nb), 256>>>();
    k3c_final<<<nb, 512>>>((float*)d_out);
}